// round 11
// baseline (speedup 1.0000x reference)
#include <cuda_runtime.h>
#include <cuda_bf16.h>
#include <math.h>
#include <stdint.h>

#define S_LEN 2048
#define EMB   2048
#define NB    2
#define NH    16
#define HD    128
#define BHN   (NB*NH)          // 32
#define M_TOT (NB*S_LEN)       // 4096

// -------- scratch (__device__ globals; no allocations allowed) --------
__device__ __nv_bfloat16 g_ah[(size_t)M_TOT * EMB]; // A hi (x, later ctx)
__device__ __nv_bfloat16 g_al[(size_t)M_TOT * EMB]; // A lo
__device__ __nv_bfloat16 g_wh[(size_t)4 * EMB * EMB]; // Wq,Wk,Wv,Wo hi
__device__ __nv_bfloat16 g_wl[(size_t)4 * EMB * EMB]; // lo
__device__ __nv_bfloat16 g_qh[(size_t)BHN * S_LEN * HD]; // rope'd Q hi
__device__ __nv_bfloat16 g_ql[(size_t)BHN * S_LEN * HD];
__device__ __nv_bfloat16 g_kh[(size_t)BHN * S_LEN * HD]; // rope'd K hi
__device__ __nv_bfloat16 g_kl[(size_t)BHN * S_LEN * HD];
__device__ __nv_bfloat16 g_vth[(size_t)BHN * HD * S_LEN]; // V^T hi (B,H,D,S)
__device__ __nv_bfloat16 g_vtl[(size_t)BHN * HD * S_LEN];

// ============================================================================
// PTX helpers (sm_80-compatible subset only: cp.async, ldmatrix, mma.sync)
// ============================================================================
__device__ __forceinline__ uint32_t smem_u32(const void* p) {
    uint32_t a;
    asm("{ .reg .u64 t; cvta.to.shared.u64 t, %1; cvt.u32.u64 %0, t; }"
        : "=r"(a) : "l"(p));
    return a;
}
__device__ __forceinline__ void cp16(uint32_t d, const void* s) {
    asm volatile("cp.async.cg.shared.global [%0], [%1], 16;" :: "r"(d), "l"(s));
}
#define CP_COMMIT() asm volatile("cp.async.commit_group;" ::: "memory")
#define CP_WAIT0()  asm volatile("cp.async.wait_group 0;" ::: "memory")
#define CP_WAIT1()  asm volatile("cp.async.wait_group 1;" ::: "memory")

__device__ __forceinline__ void ldsm4(uint32_t* r, uint32_t a) {
    asm volatile("ldmatrix.sync.aligned.m8n8.x4.shared.b16 {%0,%1,%2,%3}, [%4];"
        : "=r"(r[0]), "=r"(r[1]), "=r"(r[2]), "=r"(r[3]) : "r"(a));
}
__device__ __forceinline__ void mma16816(float* d, const uint32_t* a,
                                         uint32_t b0, uint32_t b1) {
    asm volatile(
        "mma.sync.aligned.m16n8k16.row.col.f32.bf16.bf16.f32 "
        "{%0,%1,%2,%3}, {%4,%5,%6,%7}, {%8,%9}, {%0,%1,%2,%3};"
        : "+f"(d[0]), "+f"(d[1]), "+f"(d[2]), "+f"(d[3])
        : "r"(a[0]), "r"(a[1]), "r"(a[2]), "r"(a[3]), "r"(b0), "r"(b1));
}
__device__ __forceinline__ uint32_t pack_bf16x2(float a, float b) {
    __nv_bfloat162 v = __halves2bfloat162(__float2bfloat16(a), __float2bfloat16(b));
    return *(uint32_t*)&v;
}
__device__ __forceinline__ void split_store(__nv_bfloat16* hi, __nv_bfloat16* lo,
                                            size_t off, float a, float b) {
    __nv_bfloat16 h0 = __float2bfloat16(a), h1 = __float2bfloat16(b);
    *(__nv_bfloat162*)(hi + off) = __halves2bfloat162(h0, h1);
    *(__nv_bfloat162*)(lo + off) = __halves2bfloat162(
        __float2bfloat16(a - __bfloat162float(h0)),
        __float2bfloat16(b - __bfloat162float(h1)));
}

// interleaved row-pair swizzle for 64B logical rows:
// line = row>>1 (128B), slot = ((row&1)*4 + c) ^ (line&7), c in 0..3
__device__ __forceinline__ uint32_t sw64(int row, int c) {
    int line = row >> 1;
    int slot = (((row & 1) << 2) + c) ^ (line & 7);
    return (uint32_t)(line * 128 + slot * 16);
}

// ============================================================================
// merged split: x -> ah/al, Wq..Wo -> wh/wl (single launch)
// ============================================================================
__global__ void split_all(const float4* __restrict__ x,
                          const float4* __restrict__ wq, const float4* __restrict__ wk,
                          const float4* __restrict__ wv, const float4* __restrict__ wo,
                          __nv_bfloat16* __restrict__ ah, __nv_bfloat16* __restrict__ al,
                          __nv_bfloat16* __restrict__ wh, __nv_bfloat16* __restrict__ wl,
                          int n4x, int n4w)
{
    int i = blockIdx.x * blockDim.x + threadIdx.x;
    const float4* src;
    __nv_bfloat16 *hi, *lo;
    size_t off;
    if (i < n4x) {
        src = x + i; hi = ah; lo = al; off = (size_t)i * 4;
    } else {
        int j = i - n4x;
        if (j >= 4 * n4w) return;
        int w = j / n4w;
        int r = j - w * n4w;
        src = ((w == 0) ? wq : (w == 1) ? wk : (w == 2) ? wv : wo) + r;
        hi = wh; lo = wl;
        off = ((size_t)w * n4w + r) * 4;
    }
    float4 v = *src;
    __nv_bfloat16 h0 = __float2bfloat16(v.x);
    __nv_bfloat16 h1 = __float2bfloat16(v.y);
    __nv_bfloat16 h2 = __float2bfloat16(v.z);
    __nv_bfloat16 h3 = __float2bfloat16(v.w);
    __nv_bfloat162* hp = (__nv_bfloat162*)(hi + off);
    __nv_bfloat162* lp = (__nv_bfloat162*)(lo + off);
    hp[0] = __halves2bfloat162(h0, h1);
    hp[1] = __halves2bfloat162(h2, h3);
    lp[0] = __halves2bfloat162(__float2bfloat16(v.x - __bfloat162float(h0)),
                               __float2bfloat16(v.y - __bfloat162float(h1)));
    lp[1] = __halves2bfloat162(__float2bfloat16(v.z - __bfloat162float(h2)),
                               __float2bfloat16(v.w - __bfloat162float(h3)));
}

// ============================================================================
// HMMA GEMM cores (NT), K-chunk 64, 3-stage pipeline, single sync per chunk.
// Tile 128x128, 8 warps (64x32 each).
// ============================================================================
#define STAGE_BYTES 65536
#define GEMM_SMEM   (3 * STAGE_BYTES)
#define NCH         (EMB / 64)      // 32 K-chunks

struct GemmCtx {
    float acc[4][4][4];
    int mbase, nbase, lr16, lhalf, lrow0, lck;
};

__device__ __forceinline__ void gemm_init(GemmCtx& g, int t) {
    const int lane = t & 31, warp = t >> 5;
    g.mbase = (warp >> 2) * 64;
    g.nbase = (warp & 3) * 32;
    g.lr16  = lane & 15;
    g.lhalf = lane >> 4;
    g.lrow0 = t >> 3;
    g.lck   = t & 7;
}

__device__ __forceinline__ void gemm_mainloop(
    GemmCtx& g, uint32_t sb,
    const char* pAh, const char* pAl, const char* pBh, const char* pBl)
{
    #pragma unroll
    for (int i = 0; i < 4; i++)
        #pragma unroll
        for (int j = 0; j < 4; j++)
            #pragma unroll
            for (int c = 0; c < 4; c++) g.acc[i][j][c] = 0.f;

    auto load_stage = [&](int ch, int buf) {
        const uint32_t st = sb + buf * STAGE_BYTES;
        const size_t cb = (size_t)ch * 128;
        #pragma unroll
        for (int it = 0; it < 4; it++) {
            int row = g.lrow0 + it * 32;
            uint32_t sw = (uint32_t)(row * 128 + ((g.lck ^ (row & 7)) << 4));
            size_t go = (size_t)row * (EMB * 2) + cb + g.lck * 16;
            cp16(st +         sw, pAh + go);
            cp16(st + 16384 + sw, pAl + go);
            cp16(st + 32768 + sw, pBh + go);
            cp16(st + 49152 + sw, pBl + go);
        }
    };

    load_stage(0, 0);
    CP_COMMIT();
    load_stage(1, 1);
    CP_COMMIT();

    for (int ch = 0; ch < NCH; ch++) {
        CP_WAIT1();                    // stage ch landed (g_ch complete)
        __syncthreads();               // all threads done reading stage (ch-1)%3
        if (ch + 2 < NCH) load_stage(ch + 2, (ch + 2) % 3);
        CP_COMMIT();                   // commit (possibly empty) group g_{ch+2}

        const uint32_t st = sb + (ch % 3) * STAGE_BYTES;
        const uint32_t stAh = st, stAl = st + 16384, stBh = st + 32768, stBl = st + 49152;

        #pragma unroll
        for (int ks = 0; ks < 4; ks++) {
            const int c16 = ks * 2 + g.lhalf;
            uint32_t ahf[4][4], alf[4][4], bhf[2][4], blf[2][4];
            #pragma unroll
            for (int mf = 0; mf < 4; mf++) {
                int row = g.mbase + mf * 16 + g.lr16;
                uint32_t off = (uint32_t)(row * 128 + ((c16 ^ (row & 7)) << 4));
                ldsm4(ahf[mf], stAh + off);
                ldsm4(alf[mf], stAl + off);
            }
            #pragma unroll
            for (int nf2 = 0; nf2 < 2; nf2++) {
                int row = g.nbase + nf2 * 16 + g.lr16;
                uint32_t off = (uint32_t)(row * 128 + ((c16 ^ (row & 7)) << 4));
                ldsm4(bhf[nf2], stBh + off);
                ldsm4(blf[nf2], stBl + off);
            }
            #pragma unroll
            for (int mf = 0; mf < 4; mf++) {
                #pragma unroll
                for (int nf = 0; nf < 4; nf++) {
                    uint32_t b0 = bhf[nf >> 1][nf & 1], b1 = bhf[nf >> 1][(nf & 1) + 2];
                    uint32_t l0 = blf[nf >> 1][nf & 1], l1 = blf[nf >> 1][(nf & 1) + 2];
                    mma16816(g.acc[mf][nf], ahf[mf], b0, b1);
                    mma16816(g.acc[mf][nf], ahf[mf], l0, l1);
                    mma16816(g.acc[mf][nf], alf[mf], b0, b1);
                }
            }
        }
    }
}

// ---- merged QKV GEMM: z=0 Q(rope->bf16), z=1 K(fp32 out + rope->bf16), z=2 V(fp32) ----
__global__ void __launch_bounds__(256, 1)
gemm_qkv(const __nv_bfloat16* __restrict__ Ah, const __nv_bfloat16* __restrict__ Al,
         const __nv_bfloat16* __restrict__ Wh, const __nv_bfloat16* __restrict__ Wl,
         __nv_bfloat16* __restrict__ qh, __nv_bfloat16* __restrict__ ql,
         __nv_bfloat16* __restrict__ kh, __nv_bfloat16* __restrict__ kl,
         float* __restrict__ outK, float* __restrict__ outV)
{
    extern __shared__ char smem[];
    const uint32_t sb = smem_u32(smem);
    const int t = threadIdx.x;
    const int bn = blockIdx.x, bm = blockIdx.y, z = blockIdx.z;

    GemmCtx g;
    gemm_init(g, t);
    const size_t woff = (size_t)EMB * EMB;
    gemm_mainloop(g, sb,
                  (const char*)(Ah + (size_t)bm * 128 * EMB),
                  (const char*)(Al + (size_t)bm * 128 * EMB),
                  (const char*)(Wh + z * woff + (size_t)bn * 128 * EMB),
                  (const char*)(Wl + z * woff + (size_t)bn * 128 * EMB));

    const int lane = t & 31;
    const int gid = lane >> 2, qd = lane & 3;

    if (z == 2) {
        #pragma unroll
        for (int mf = 0; mf < 4; mf++)
            #pragma unroll
            for (int half = 0; half < 2; half++) {
                int row = bm * 128 + g.mbase + mf * 16 + half * 8 + gid;
                int b = row >> 11, s = row & (S_LEN - 1);
                float* dst = outV + (((size_t)(b * NH + bn) * S_LEN + s) << 7);
                #pragma unroll
                for (int nf = 0; nf < 4; nf++) {
                    int col = g.nbase + nf * 8 + qd * 2;
                    *(float2*)(dst + col) = make_float2(g.acc[mf][nf][half*2],
                                                        g.acc[mf][nf][half*2+1]);
                }
            }
        return;
    }

    // Q/K: RoPE + bf16 hi/lo split epilogue (pair = (d, d+1), d even)
    float fr[4];
    #pragma unroll
    for (int nf = 0; nf < 4; nf++) {
        int d = g.nbase + nf * 8 + qd * 2;
        fr[nf] = powf(10000.0f, -(float)d / 128.0f);
    }
    __nv_bfloat16* oh = (z == 0) ? qh : kh;
    __nv_bfloat16* ol = (z == 0) ? ql : kl;
    #pragma unroll
    for (int mf = 0; mf < 4; mf++)
        #pragma unroll
        for (int half = 0; half < 2; half++) {
            int row = bm * 128 + g.mbase + mf * 16 + half * 8 + gid;
            int b = row >> 11, s = row & (S_LEN - 1);
            size_t base = ((size_t)(b * NH + bn) * S_LEN + s) << 7;
            #pragma unroll
            for (int nf = 0; nf < 4; nf++) {
                int d = g.nbase + nf * 8 + qd * 2;
                float x1 = g.acc[mf][nf][half*2], x2 = g.acc[mf][nf][half*2+1];
                if (z == 1)
                    *(float2*)(outK + base + d) = make_float2(x1, x2);
                float sn, cs;
                sincosf((float)s * fr[nf], &sn, &cs);
                split_store(oh, ol, base + d, x1 * cs - x2 * sn, x1 * sn + x2 * cs);
            }
        }
}

// ---- Wo GEMM: row-major fp32 out ----
__global__ void __launch_bounds__(256, 1)
gemm_wo(const __nv_bfloat16* __restrict__ Ah, const __nv_bfloat16* __restrict__ Al,
        const __nv_bfloat16* __restrict__ Bh, const __nv_bfloat16* __restrict__ Bl,
        float* __restrict__ C)
{
    extern __shared__ char smem[];
    const uint32_t sb = smem_u32(smem);
    const int t = threadIdx.x;
    const int bn = blockIdx.x, bm = blockIdx.y;

    GemmCtx g;
    gemm_init(g, t);
    gemm_mainloop(g, sb,
                  (const char*)(Ah + (size_t)bm * 128 * EMB),
                  (const char*)(Al + (size_t)bm * 128 * EMB),
                  (const char*)(Bh + (size_t)bn * 128 * EMB),
                  (const char*)(Bl + (size_t)bn * 128 * EMB));

    const int lane = t & 31;
    const int gid = lane >> 2, qd = lane & 3;
    #pragma unroll
    for (int mf = 0; mf < 4; mf++)
        #pragma unroll
        for (int half = 0; half < 2; half++) {
            int row = bm * 128 + g.mbase + mf * 16 + half * 8 + gid;
            float* dst = C + (size_t)row * EMB + bn * 128;
            #pragma unroll
            for (int nf = 0; nf < 4; nf++) {
                int col = g.nbase + nf * 8 + qd * 2;
                *(float2*)(dst + col) = make_float2(g.acc[mf][nf][half*2],
                                                    g.acc[mf][nf][half*2+1]);
            }
        }
}

// ============================================================================
// V transpose + split: (B,H,S,D) fp32 -> (B,H,D,S) bf16 hi/lo
// ============================================================================
__global__ void vsplit_t(const float* __restrict__ v,
                         __nv_bfloat16* __restrict__ vth, __nv_bfloat16* __restrict__ vtl)
{
    __shared__ float tile[32][33];
    int tx = threadIdx.x, ty = threadIdx.y;     // block (32, 8)
    int s0 = blockIdx.x * 32, d0 = blockIdx.y * 32, bh = blockIdx.z;

    #pragma unroll
    for (int k = 0; k < 4; k++) {
        int s = s0 + ty + k * 8;
        tile[ty + k * 8][tx] = v[((size_t)bh * S_LEN + s) * HD + d0 + tx];
    }
    __syncthreads();
    #pragma unroll
    for (int k = 0; k < 4; k++) {
        int d = d0 + ty + k * 8;
        float x = tile[tx][ty + k * 8];
        __nv_bfloat16 h = __float2bfloat16(x);
        size_t o = ((size_t)bh * HD + d) * S_LEN + s0 + tx;
        vth[o] = h;
        vtl[o] = __float2bfloat16(x - __bfloat162float(h));
    }
}

// ============================================================================
// HMMA flash attention (causal). BM=64, BN=32, 128 threads, 2 CTAs/SM.
// Software-pipelined: PV(j-1) (P carried in regs) issued after S(j).
// Single barrier per iter; all stage overwrites happen post-barrier (race-free):
//   iter j: wait0 -> sync -> issue load(j+1) -> S(j) -> PV(j-1) -> softmax/pack
// smem: Qh [0,16K) Ql [16K,32K) | K 2 stages @32K (16K each: Kh 8K, Kl 8K)
//       | V 3 stages @64K (16K each).  Total 112K -> 2 CTAs/SM.
// ============================================================================
#define A_SK 32768
#define A_SV 65536
#define ATT_SMEM (65536 + 3*16384)   // 114688

__global__ void __launch_bounds__(128, 2)
attn_mma(const __nv_bfloat16* __restrict__ qh, const __nv_bfloat16* __restrict__ ql,
         const __nv_bfloat16* __restrict__ kh, const __nv_bfloat16* __restrict__ kl,
         const __nv_bfloat16* __restrict__ vth, const __nv_bfloat16* __restrict__ vtl,
         __nv_bfloat16* __restrict__ ch, __nv_bfloat16* __restrict__ cl)
{
    extern __shared__ char smem[];
    const uint32_t sb = smem_u32(smem);
    const int t    = threadIdx.x;
    const int lane = t & 31;
    const int w    = t >> 5;                                 // 0..3
    const int qt   = (int)gridDim.x - 1 - (int)blockIdx.x;   // heavy tiles first
    const int bh   = blockIdx.y;

    const int lr16  = lane & 15;
    const int lhalf = lane >> 4;
    const int gid   = lane >> 2;
    const int qd    = lane & 3;

    // ---- load Q tile (64 x 128 bf16, hi+lo), once ----
    #pragma unroll
    for (int it = 0; it < 8; it++) {
        int idx = t + it * 128;
        int row = idx >> 4, c = idx & 15;
        uint32_t sw = (uint32_t)(row * 256 + ((c ^ (row & 7)) << 4));
        size_t gq = (((size_t)bh * S_LEN) + qt * 64 + row) * HD + c * 8;
        cp16(sb +         sw, qh + gq);
        cp16(sb + 16384 + sw, ql + gq);
    }

    auto load_kv = [&](int j, int kb, int vb) {
        const uint32_t stK = sb + A_SK + kb * 16384;
        const uint32_t stV = sb + A_SV + vb * 16384;
        #pragma unroll
        for (int it = 0; it < 4; it++) {
            int idx = t + it * 128;
            int rowK = idx >> 4, cK = idx & 15;              // 32 rows x 16 chunks
            uint32_t swK = (uint32_t)(rowK * 256 + ((cK ^ (rowK & 7)) << 4));
            size_t gk = (((size_t)bh * S_LEN) + j * 32 + rowK) * HD + cK * 8;
            cp16(stK +        swK, kh + gk);
            cp16(stK + 8192 + swK, kl + gk);
            int rowV = idx >> 2, cV = idx & 3;               // 128 D-rows x 4 chunks
            uint32_t swV = sw64(rowV, cV);
            size_t gv = (((size_t)bh * HD) + rowV) * S_LEN + j * 32 + cV * 8;
            cp16(stV +        swV, vth + gv);
            cp16(stV + 8192 + swV, vtl + gv);
        }
    };

    load_kv(0, 0, 0);
    CP_COMMIT();

    float oacc[16][4];
    #pragma unroll
    for (int i = 0; i < 16; i++)
        #pragma unroll
        for (int c = 0; c < 4; c++) oacc[i][c] = 0.f;
    float mp0 = -1e30f, mp1 = -1e30f, ls0 = 0.f, ls1 = 0.f;
    uint32_t ppa[2][4], ppb[2][4];   // carried P (hi / residual, packed bf16x2)

    const float scale = 0.088388347648318447f;  // 1/sqrt(128)
    const int jmax = 2 * qt + 1;
    const int row0g = qt * 64 + w * 16 + gid;
    const int row1g = row0g + 8;

    auto do_pv = [&](int vb) {
        const uint32_t stVh = sb + A_SV + vb * 16384;
        const uint32_t stVl = stVh + 8192;
        #pragma unroll
        for (int ks = 0; ks < 2; ks++) {
            const int c = ks * 2 + lhalf;
            #pragma unroll
            for (int nb = 0; nb < 8; nb++) {
                int rowB = nb * 16 + lr16;
                uint32_t offB = sw64(rowB, c);
                uint32_t vh4[4], vl4[4];
                ldsm4(vh4, stVh + offB);
                ldsm4(vl4, stVl + offB);
                mma16816(oacc[2*nb],   ppa[ks], vh4[0], vh4[2]);
                mma16816(oacc[2*nb],   ppa[ks], vl4[0], vl4[2]);
                mma16816(oacc[2*nb],   ppb[ks], vh4[0], vh4[2]);
                mma16816(oacc[2*nb+1], ppa[ks], vh4[1], vh4[3]);
                mma16816(oacc[2*nb+1], ppa[ks], vl4[1], vl4[3]);
                mma16816(oacc[2*nb+1], ppb[ks], vh4[1], vh4[3]);
            }
        }
    };

    for (int j = 0; j <= jmax; j++) {
        CP_WAIT0();        // stage j (K and V) fully landed
        __syncthreads();   // all threads done with iter j-1 reads; safe to overwrite
        if (j + 1 <= jmax) load_kv(j + 1, (j + 1) & 1, (j + 1) % 3);
        CP_COMMIT();

        const uint32_t stKh = sb + A_SK + (j & 1) * 16384;
        const uint32_t stKl = stKh + 8192;

        // ---- S = Q K^T (warp: 16 rows x 32 cols) ----
        float sacc[4][4];
        #pragma unroll
        for (int i = 0; i < 4; i++)
            #pragma unroll
            for (int c = 0; c < 4; c++) sacc[i][c] = 0.f;

        #pragma unroll
        for (int kd = 0; kd < 8; kd++) {
            const int c16 = kd * 2 + lhalf;
            int rowA = w * 16 + lr16;
            uint32_t offA = (uint32_t)(rowA * 256 + ((c16 ^ (rowA & 7)) << 4));
            uint32_t ah4[4], al4[4];
            ldsm4(ah4, sb +         offA);
            ldsm4(al4, sb + 16384 + offA);
            #pragma unroll
            for (int nb = 0; nb < 2; nb++) {
                int rowB = nb * 16 + lr16;
                uint32_t offB = (uint32_t)(rowB * 256 + ((c16 ^ (rowB & 7)) << 4));
                uint32_t bh4[4], bl4[4];
                ldsm4(bh4, stKh + offB);
                ldsm4(bl4, stKl + offB);
                mma16816(sacc[2*nb],   ah4, bh4[0], bh4[2]);
                mma16816(sacc[2*nb],   ah4, bl4[0], bl4[2]);
                mma16816(sacc[2*nb],   al4, bh4[0], bh4[2]);
                mma16816(sacc[2*nb+1], ah4, bh4[1], bh4[3]);
                mma16816(sacc[2*nb+1], ah4, bl4[1], bl4[3]);
                mma16816(sacc[2*nb+1], al4, bh4[1], bh4[3]);
            }
        }

        // ---- PV for previous tile (P carried in regs); overlaps softmax deps ----
        if (j > 0) do_pv((j - 1) % 3);

        // ---- online softmax ----
        const bool need_mask = (j * 32 + 31) > (qt * 64 + w * 16);
        float mx0 = -1e30f, mx1 = -1e30f;
        #pragma unroll
        for (int nf = 0; nf < 4; nf++) {
            int colg = j * 32 + nf * 8 + qd * 2;
            float v0 = sacc[nf][0] * scale;
            float v1 = sacc[nf][1] * scale;
            float v2 = sacc[nf][2] * scale;
            float v3 = sacc[nf][3] * scale;
            if (need_mask) {
                if (colg     > row0g) v0 = -1e30f;
                if (colg + 1 > row0g) v1 = -1e30f;
                if (colg     > row1g) v2 = -1e30f;
                if (colg + 1 > row1g) v3 = -1e30f;
            }
            sacc[nf][0] = v0; sacc[nf][1] = v1; sacc[nf][2] = v2; sacc[nf][3] = v3;
            mx0 = fmaxf(mx0, fmaxf(v0, v1));
            mx1 = fmaxf(mx1, fmaxf(v2, v3));
        }
        mx0 = fmaxf(mx0, __shfl_xor_sync(0xffffffffu, mx0, 1));
        mx0 = fmaxf(mx0, __shfl_xor_sync(0xffffffffu, mx0, 2));
        mx1 = fmaxf(mx1, __shfl_xor_sync(0xffffffffu, mx1, 1));
        mx1 = fmaxf(mx1, __shfl_xor_sync(0xffffffffu, mx1, 2));
        float mn0 = fmaxf(mp0, mx0), mn1 = fmaxf(mp1, mx1);
        float a0 = __expf(mp0 - mn0), a1 = __expf(mp1 - mn1);
        mp0 = mn0; mp1 = mn1;
        float pl0 = 0.f, pl1 = 0.f;
        #pragma unroll
        for (int nf = 0; nf < 4; nf++) {
            float p0 = __expf(sacc[nf][0] - mn0);
            float p1 = __expf(sacc[nf][1] - mn0);
            float p2 = __expf(sacc[nf][2] - mn1);
            float p3 = __expf(sacc[nf][3] - mn1);
            sacc[nf][0] = p0; sacc[nf][1] = p1; sacc[nf][2] = p2; sacc[nf][3] = p3;
            pl0 += p0 + p1; pl1 += p2 + p3;
        }
        ls0 = ls0 * a0 + pl0;
        ls1 = ls1 * a1 + pl1;
        #pragma unroll
        for (int nf = 0; nf < 16; nf++) {
            oacc[nf][0] *= a0; oacc[nf][1] *= a0;
            oacc[nf][2] *= a1; oacc[nf][3] *= a1;
        }

        // ---- pack P (hi + residual) into carried registers ----
        #pragma unroll
        for (int ks = 0; ks < 2; ks++) {
            float p00 = sacc[2*ks][0],   p01 = sacc[2*ks][1];
            float p02 = sacc[2*ks][2],   p03 = sacc[2*ks][3];
            float p10 = sacc[2*ks+1][0], p11 = sacc[2*ks+1][1];
            float p12 = sacc[2*ks+1][2], p13 = sacc[2*ks+1][3];
            ppa[ks][0] = pack_bf16x2(p00, p01);
            ppa[ks][1] = pack_bf16x2(p02, p03);
            ppa[ks][2] = pack_bf16x2(p10, p11);
            ppa[ks][3] = pack_bf16x2(p12, p13);
            __nv_bfloat162 h;
            h = *(__nv_bfloat162*)&ppa[ks][0];
            ppb[ks][0] = pack_bf16x2(p00 - __bfloat162float(h.x), p01 - __bfloat162float(h.y));
            h = *(__nv_bfloat162*)&ppa[ks][1];
            ppb[ks][1] = pack_bf16x2(p02 - __bfloat162float(h.x), p03 - __bfloat162float(h.y));
            h = *(__nv_bfloat162*)&ppa[ks][2];
            ppb[ks][2] = pack_bf16x2(p10 - __bfloat162float(h.x), p11 - __bfloat162float(h.y));
            h = *(__nv_bfloat162*)&ppa[ks][3];
            ppb[ks][3] = pack_bf16x2(p12 - __bfloat162float(h.x), p13 - __bfloat162float(h.y));
        }
    }

    // ---- final PV for tile jmax ----
    do_pv(jmax % 3);

    // ---- finalize + fused bf16 hi/lo ctx write (B,S,E) ----
    ls0 += __shfl_xor_sync(0xffffffffu, ls0, 1);
    ls0 += __shfl_xor_sync(0xffffffffu, ls0, 2);
    ls1 += __shfl_xor_sync(0xffffffffu, ls1, 1);
    ls1 += __shfl_xor_sync(0xffffffffu, ls1, 2);
    float rn0 = 1.f / ls0, rn1 = 1.f / ls1;

    int b = bh >> 4, h = bh & 15;
    size_t e0 = ((size_t)b * S_LEN + row0g) * EMB + h * HD;
    size_t e1 = e0 + (size_t)8 * EMB;
    #pragma unroll
    for (int nf = 0; nf < 16; nf++) {
        int col = nf * 8 + qd * 2;
        split_store(ch, cl, e0 + col, oacc[nf][0] * rn0, oacc[nf][1] * rn0);
        split_store(ch, cl, e1 + col, oacc[nf][2] * rn1, oacc[nf][3] * rn1);
    }
}

// ============================================================================
// launch
// ============================================================================
extern "C" void kernel_launch(void* const* d_in, const int* in_sizes, int n_in,
                              void* d_out, int out_size)
{
    (void)in_sizes; (void)n_in; (void)out_size;
    const float* x  = (const float*)d_in[0];
    const float* Wq = (const float*)d_in[1];
    const float* Wk = (const float*)d_in[2];
    const float* Wv = (const float*)d_in[3];
    const float* Wo = (const float*)d_in[4];

    float* out  = (float*)d_out;
    float* outK = out  + (size_t)NB * S_LEN * EMB;
    float* outV = outK + (size_t)BHN * S_LEN * HD;

    __nv_bfloat16 *ah, *al, *wh, *wl, *qhp, *qlp, *khp, *klp, *vthp, *vtlp;
    cudaGetSymbolAddress((void**)&ah,   g_ah);
    cudaGetSymbolAddress((void**)&al,   g_al);
    cudaGetSymbolAddress((void**)&wh,   g_wh);
    cudaGetSymbolAddress((void**)&wl,   g_wl);
    cudaGetSymbolAddress((void**)&qhp,  g_qh);
    cudaGetSymbolAddress((void**)&qlp,  g_ql);
    cudaGetSymbolAddress((void**)&khp,  g_kh);
    cudaGetSymbolAddress((void**)&klp,  g_kl);
    cudaGetSymbolAddress((void**)&vthp, g_vth);
    cudaGetSymbolAddress((void**)&vtlp, g_vtl);

    cudaFuncSetAttribute(attn_mma,
                         cudaFuncAttributeMaxDynamicSharedMemorySize, ATT_SMEM);
    cudaFuncSetAttribute(gemm_qkv,
                         cudaFuncAttributeMaxDynamicSharedMemorySize, GEMM_SMEM);
    cudaFuncSetAttribute(gemm_wo,
                         cudaFuncAttributeMaxDynamicSharedMemorySize, GEMM_SMEM);

    const size_t woff = (size_t)EMB * EMB;

    int n4x = M_TOT * EMB / 4;
    int n4w = EMB * EMB / 4;
    int n4tot = n4x + 4 * n4w;
    split_all<<<(n4tot + 255) / 256, 256>>>((const float4*)x,
        (const float4*)Wq, (const float4*)Wk, (const float4*)Wv, (const float4*)Wo,
        ah, al, wh, wl, n4x, n4w);

    // fused QKV projection (+RoPE/split for Q,K), one launch
    gemm_qkv<<<dim3(EMB / 128, M_TOT / 128, 3), 256, GEMM_SMEM>>>(
        ah, al, wh, wl, qhp, qlp, khp, klp, outK, outV);

    vsplit_t<<<dim3(S_LEN / 32, HD / 32, BHN), dim3(32, 8)>>>(outV, vthp, vtlp);

    // attention writes ctx directly as bf16 hi/lo into ah/al
    attn_mma<<<dim3(S_LEN / 64, BHN), 128, ATT_SMEM>>>(qhp, qlp, khp, klp,
                                                       vthp, vtlp, ah, al);

    gemm_wo<<<dim3(EMB / 128, M_TOT / 128), 256, GEMM_SMEM>>>(
        ah, al, wh + 3*woff, wl + 3*woff, out);
}

// round 12
// speedup vs baseline: 1.7002x; 1.7002x over previous
#include <cuda_runtime.h>
#include <cuda_bf16.h>
#include <math.h>
#include <stdint.h>

#define S_LEN 2048
#define EMB   2048
#define NB    2
#define NH    16
#define HD    128
#define BHN   (NB*NH)          // 32
#define M_TOT (NB*S_LEN)       // 4096

// -------- scratch (__device__ globals; no allocations allowed) --------
__device__ __nv_bfloat16 g_ah[(size_t)M_TOT * EMB]; // A hi (x, later ctx)
__device__ __nv_bfloat16 g_al[(size_t)M_TOT * EMB]; // A lo
__device__ __nv_bfloat16 g_wh[(size_t)4 * EMB * EMB]; // Wq,Wk,Wv,Wo hi
__device__ __nv_bfloat16 g_wl[(size_t)4 * EMB * EMB]; // lo
__device__ __nv_bfloat16 g_qh[(size_t)BHN * S_LEN * HD]; // rope'd Q hi
__device__ __nv_bfloat16 g_ql[(size_t)BHN * S_LEN * HD];
__device__ __nv_bfloat16 g_kh[(size_t)BHN * S_LEN * HD]; // rope'd K hi
__device__ __nv_bfloat16 g_kl[(size_t)BHN * S_LEN * HD];
__device__ __nv_bfloat16 g_vth[(size_t)BHN * HD * S_LEN]; // V^T hi (B,H,D,S)
__device__ __nv_bfloat16 g_vtl[(size_t)BHN * HD * S_LEN];

// ============================================================================
// PTX helpers (sm_80-compatible subset only: cp.async, ldmatrix, mma.sync)
// ============================================================================
__device__ __forceinline__ uint32_t smem_u32(const void* p) {
    uint32_t a;
    asm("{ .reg .u64 t; cvta.to.shared.u64 t, %1; cvt.u32.u64 %0, t; }"
        : "=r"(a) : "l"(p));
    return a;
}
__device__ __forceinline__ void cp16(uint32_t d, const void* s) {
    asm volatile("cp.async.cg.shared.global [%0], [%1], 16;" :: "r"(d), "l"(s));
}
#define CP_COMMIT() asm volatile("cp.async.commit_group;" ::: "memory")
#define CP_WAIT1()  asm volatile("cp.async.wait_group 1;" ::: "memory")

__device__ __forceinline__ void ldsm4(uint32_t* r, uint32_t a) {
    asm volatile("ldmatrix.sync.aligned.m8n8.x4.shared.b16 {%0,%1,%2,%3}, [%4];"
        : "=r"(r[0]), "=r"(r[1]), "=r"(r[2]), "=r"(r[3]) : "r"(a));
}
__device__ __forceinline__ void mma16816(float* d, const uint32_t* a,
                                         uint32_t b0, uint32_t b1) {
    asm volatile(
        "mma.sync.aligned.m16n8k16.row.col.f32.bf16.bf16.f32 "
        "{%0,%1,%2,%3}, {%4,%5,%6,%7}, {%8,%9}, {%0,%1,%2,%3};"
        : "+f"(d[0]), "+f"(d[1]), "+f"(d[2]), "+f"(d[3])
        : "r"(a[0]), "r"(a[1]), "r"(a[2]), "r"(a[3]), "r"(b0), "r"(b1));
}
__device__ __forceinline__ uint32_t pack_bf16x2(float a, float b) {
    __nv_bfloat162 v = __halves2bfloat162(__float2bfloat16(a), __float2bfloat16(b));
    return *(uint32_t*)&v;
}
__device__ __forceinline__ void split_store(__nv_bfloat16* hi, __nv_bfloat16* lo,
                                            size_t off, float a, float b) {
    __nv_bfloat16 h0 = __float2bfloat16(a), h1 = __float2bfloat16(b);
    *(__nv_bfloat162*)(hi + off) = __halves2bfloat162(h0, h1);
    *(__nv_bfloat162*)(lo + off) = __halves2bfloat162(
        __float2bfloat16(a - __bfloat162float(h0)),
        __float2bfloat16(b - __bfloat162float(h1)));
}

// interleaved row-pair swizzle for 64B logical rows:
// line = row>>1 (128B), slot = ((row&1)*4 + c) ^ (line&7), c in 0..3
__device__ __forceinline__ uint32_t sw64(int row, int c) {
    int line = row >> 1;
    int slot = (((row & 1) << 2) + c) ^ (line & 7);
    return (uint32_t)(line * 128 + slot * 16);
}

// ============================================================================
// merged split: x -> ah/al, Wq..Wo -> wh/wl (single launch)
// ============================================================================
__global__ void split_all(const float4* __restrict__ x,
                          const float4* __restrict__ wq, const float4* __restrict__ wk,
                          const float4* __restrict__ wv, const float4* __restrict__ wo,
                          __nv_bfloat16* __restrict__ ah, __nv_bfloat16* __restrict__ al,
                          __nv_bfloat16* __restrict__ wh, __nv_bfloat16* __restrict__ wl,
                          int n4x, int n4w)
{
    int i = blockIdx.x * blockDim.x + threadIdx.x;
    const float4* src;
    __nv_bfloat16 *hi, *lo;
    size_t off;
    if (i < n4x) {
        src = x + i; hi = ah; lo = al; off = (size_t)i * 4;
    } else {
        int j = i - n4x;
        if (j >= 4 * n4w) return;
        int w = j / n4w;
        int r = j - w * n4w;
        src = ((w == 0) ? wq : (w == 1) ? wk : (w == 2) ? wv : wo) + r;
        hi = wh; lo = wl;
        off = ((size_t)w * n4w + r) * 4;
    }
    float4 v = *src;
    __nv_bfloat16 h0 = __float2bfloat16(v.x);
    __nv_bfloat16 h1 = __float2bfloat16(v.y);
    __nv_bfloat16 h2 = __float2bfloat16(v.z);
    __nv_bfloat16 h3 = __float2bfloat16(v.w);
    __nv_bfloat162* hp = (__nv_bfloat162*)(hi + off);
    __nv_bfloat162* lp = (__nv_bfloat162*)(lo + off);
    hp[0] = __halves2bfloat162(h0, h1);
    hp[1] = __halves2bfloat162(h2, h3);
    lp[0] = __halves2bfloat162(__float2bfloat16(v.x - __bfloat162float(h0)),
                               __float2bfloat16(v.y - __bfloat162float(h1)));
    lp[1] = __halves2bfloat162(__float2bfloat16(v.z - __bfloat162float(h2)),
                               __float2bfloat16(v.w - __bfloat162float(h3)));
}

// ============================================================================
// HMMA GEMM cores (NT), K-chunk 64, 2-stage pipeline, 128-thr CTAs, 2 CTAs/SM.
// CTA tile 128x64 (A rows x B rows), 4 warps each 64x32.
// Stage 48KB: Ah[0,16K) Al[16K,32K) Bh[32K,40K) Bl[40K,48K).
// Prefetch-before-wait ordering (proven R8/R10); end-of-iter sync closes
// the stage-overwrite hazard (load(ch+1) writes (ch-1)&1, read pre-sync).
// ============================================================================
#define STG       49152
#define GEMM_SMEM (2 * STG)         // 96KB -> 2 CTAs/SM
#define NCH       (EMB / 64)        // 32 K-chunks

struct GemmCtx {
    float acc[4][4][4];
    int mbase, nbase, lr16, lhalf;
};

__device__ __forceinline__ void gemm_init(GemmCtx& g, int t) {
    const int lane = t & 31, warp = t >> 5;
    g.mbase = (warp >> 1) * 64;     // 0 / 64
    g.nbase = (warp & 1) * 32;      // 0 / 32
    g.lr16  = lane & 15;
    g.lhalf = lane >> 4;
}

__device__ __forceinline__ void gemm_mainloop(
    GemmCtx& g, uint32_t sb, int t,
    const char* pAh, const char* pAl, const char* pBh, const char* pBl)
{
    #pragma unroll
    for (int i = 0; i < 4; i++)
        #pragma unroll
        for (int j = 0; j < 4; j++)
            #pragma unroll
            for (int c = 0; c < 4; c++) g.acc[i][j][c] = 0.f;

    auto load_stage = [&](int ch, int buf) {
        const uint32_t st = sb + buf * STG;
        const size_t cb = (size_t)ch * 128;     // 64 bf16 = 128B along K
        #pragma unroll
        for (int it = 0; it < 8; it++) {
            int idx = t + it * 128;
            int row = idx >> 3, ck = idx & 7;   // A: 128 rows x 8 chunks
            uint32_t sw = (uint32_t)(row * 128 + ((ck ^ (row & 7)) << 4));
            size_t go = (size_t)row * (EMB * 2) + cb + ck * 16;
            cp16(st +         sw, pAh + go);
            cp16(st + 16384 + sw, pAl + go);
            if (row < 64) {                      // B: 64 rows x 8 chunks
                cp16(st + 32768 + sw, pBh + go);
                cp16(st + 40960 + sw, pBl + go);
            }
        }
    };

    load_stage(0, 0);
    CP_COMMIT();

    for (int ch = 0; ch < NCH; ch++) {
        if (ch + 1 < NCH) load_stage(ch + 1, (ch + 1) & 1);
        CP_COMMIT();
        CP_WAIT1();                  // stage ch landed; stage ch+1 in flight
        __syncthreads();

        const uint32_t st = sb + (ch & 1) * STG;
        const uint32_t stAh = st, stAl = st + 16384, stBh = st + 32768, stBl = st + 40960;

        #pragma unroll
        for (int ks = 0; ks < 4; ks++) {
            const int c16 = ks * 2 + g.lhalf;
            uint32_t ahf[4][4], alf[4][4], bhf[2][4], blf[2][4];
            #pragma unroll
            for (int mf = 0; mf < 4; mf++) {
                int row = g.mbase + mf * 16 + g.lr16;
                uint32_t off = (uint32_t)(row * 128 + ((c16 ^ (row & 7)) << 4));
                ldsm4(ahf[mf], stAh + off);
                ldsm4(alf[mf], stAl + off);
            }
            #pragma unroll
            for (int nf2 = 0; nf2 < 2; nf2++) {
                int row = g.nbase + nf2 * 16 + g.lr16;
                uint32_t off = (uint32_t)(row * 128 + ((c16 ^ (row & 7)) << 4));
                ldsm4(bhf[nf2], stBh + off);
                ldsm4(blf[nf2], stBl + off);
            }
            #pragma unroll
            for (int mf = 0; mf < 4; mf++) {
                #pragma unroll
                for (int nf = 0; nf < 4; nf++) {
                    uint32_t b0 = bhf[nf >> 1][nf & 1], b1 = bhf[nf >> 1][(nf & 1) + 2];
                    uint32_t l0 = blf[nf >> 1][nf & 1], l1 = blf[nf >> 1][(nf & 1) + 2];
                    mma16816(g.acc[mf][nf], ahf[mf], b0, b1);
                    mma16816(g.acc[mf][nf], ahf[mf], l0, l1);
                    mma16816(g.acc[mf][nf], alf[mf], b0, b1);
                }
            }
        }
        __syncthreads();             // readers done before next iter's overwrite
    }
}

// ---- merged QKV GEMM: z=0 Q(rope->bf16), z=1 K(fp32 out + rope->bf16), z=2 V(fp32) ----
__global__ void __launch_bounds__(128, 2)
gemm_qkv(const __nv_bfloat16* __restrict__ Ah, const __nv_bfloat16* __restrict__ Al,
         const __nv_bfloat16* __restrict__ Wh, const __nv_bfloat16* __restrict__ Wl,
         __nv_bfloat16* __restrict__ qh, __nv_bfloat16* __restrict__ ql,
         __nv_bfloat16* __restrict__ kh, __nv_bfloat16* __restrict__ kl,
         float* __restrict__ outK, float* __restrict__ outV)
{
    extern __shared__ char smem[];
    const uint32_t sb = smem_u32(smem);
    const int t = threadIdx.x;
    const int bn = blockIdx.x, bm = blockIdx.y, z = blockIdx.z;

    GemmCtx g;
    gemm_init(g, t);
    const size_t woff = (size_t)EMB * EMB;
    gemm_mainloop(g, sb, t,
                  (const char*)(Ah + (size_t)bm * 128 * EMB),
                  (const char*)(Al + (size_t)bm * 128 * EMB),
                  (const char*)(Wh + z * woff + (size_t)bn * 64 * EMB),
                  (const char*)(Wl + z * woff + (size_t)bn * 64 * EMB));

    const int lane = t & 31;
    const int gid = lane >> 2, qd = lane & 3;
    const int head = bn >> 1;
    const int hd2  = (bn & 1) * 64;

    if (z == 2) {
        #pragma unroll
        for (int mf = 0; mf < 4; mf++)
            #pragma unroll
            for (int half = 0; half < 2; half++) {
                int row = bm * 128 + g.mbase + mf * 16 + half * 8 + gid;
                int b = row >> 11, s = row & (S_LEN - 1);
                float* dst = outV + (((size_t)(b * NH + head) * S_LEN + s) << 7);
                #pragma unroll
                for (int nf = 0; nf < 4; nf++) {
                    int d = hd2 + g.nbase + nf * 8 + qd * 2;
                    *(float2*)(dst + d) = make_float2(g.acc[mf][nf][half*2],
                                                      g.acc[mf][nf][half*2+1]);
                }
            }
        return;
    }

    // Q/K: RoPE + bf16 hi/lo split epilogue (pair = (d, d+1), d even)
    float fr[4];
    #pragma unroll
    for (int nf = 0; nf < 4; nf++) {
        int d = hd2 + g.nbase + nf * 8 + qd * 2;
        fr[nf] = powf(10000.0f, -(float)d / 128.0f);
    }
    __nv_bfloat16* oh = (z == 0) ? qh : kh;
    __nv_bfloat16* ol = (z == 0) ? ql : kl;
    #pragma unroll
    for (int mf = 0; mf < 4; mf++)
        #pragma unroll
        for (int half = 0; half < 2; half++) {
            int row = bm * 128 + g.mbase + mf * 16 + half * 8 + gid;
            int b = row >> 11, s = row & (S_LEN - 1);
            size_t base = ((size_t)(b * NH + head) * S_LEN + s) << 7;
            #pragma unroll
            for (int nf = 0; nf < 4; nf++) {
                int d = hd2 + g.nbase + nf * 8 + qd * 2;
                float x1 = g.acc[mf][nf][half*2], x2 = g.acc[mf][nf][half*2+1];
                if (z == 1)
                    *(float2*)(outK + base + d) = make_float2(x1, x2);
                float sn, cs;
                sincosf((float)s * fr[nf], &sn, &cs);
                split_store(oh, ol, base + d, x1 * cs - x2 * sn, x1 * sn + x2 * cs);
            }
        }
}

// ---- Wo GEMM: row-major fp32 out ----
__global__ void __launch_bounds__(128, 2)
gemm_wo(const __nv_bfloat16* __restrict__ Ah, const __nv_bfloat16* __restrict__ Al,
        const __nv_bfloat16* __restrict__ Bh, const __nv_bfloat16* __restrict__ Bl,
        float* __restrict__ C)
{
    extern __shared__ char smem[];
    const uint32_t sb = smem_u32(smem);
    const int t = threadIdx.x;
    const int bn = blockIdx.x, bm = blockIdx.y;

    GemmCtx g;
    gemm_init(g, t);
    gemm_mainloop(g, sb, t,
                  (const char*)(Ah + (size_t)bm * 128 * EMB),
                  (const char*)(Al + (size_t)bm * 128 * EMB),
                  (const char*)(Bh + (size_t)bn * 64 * EMB),
                  (const char*)(Bl + (size_t)bn * 64 * EMB));

    const int lane = t & 31;
    const int gid = lane >> 2, qd = lane & 3;
    #pragma unroll
    for (int mf = 0; mf < 4; mf++)
        #pragma unroll
        for (int half = 0; half < 2; half++) {
            int row = bm * 128 + g.mbase + mf * 16 + half * 8 + gid;
            float* dst = C + (size_t)row * EMB + bn * 64;
            #pragma unroll
            for (int nf = 0; nf < 4; nf++) {
                int col = g.nbase + nf * 8 + qd * 2;
                *(float2*)(dst + col) = make_float2(g.acc[mf][nf][half*2],
                                                    g.acc[mf][nf][half*2+1]);
            }
        }
}

// ============================================================================
// V transpose + split: (B,H,S,D) fp32 -> (B,H,D,S) bf16 hi/lo
// ============================================================================
__global__ void vsplit_t(const float* __restrict__ v,
                         __nv_bfloat16* __restrict__ vth, __nv_bfloat16* __restrict__ vtl)
{
    __shared__ float tile[32][33];
    int tx = threadIdx.x, ty = threadIdx.y;     // block (32, 8)
    int s0 = blockIdx.x * 32, d0 = blockIdx.y * 32, bh = blockIdx.z;

    #pragma unroll
    for (int k = 0; k < 4; k++) {
        int s = s0 + ty + k * 8;
        tile[ty + k * 8][tx] = v[((size_t)bh * S_LEN + s) * HD + d0 + tx];
    }
    __syncthreads();
    #pragma unroll
    for (int k = 0; k < 4; k++) {
        int d = d0 + ty + k * 8;
        float x = tile[tx][ty + k * 8];
        __nv_bfloat16 h = __float2bfloat16(x);
        size_t o = ((size_t)bh * HD + d) * S_LEN + s0 + tx;
        vth[o] = h;
        vtl[o] = __float2bfloat16(x - __bfloat162float(h));
    }
}

// ============================================================================
// HMMA flash attention (causal). BM=64, BN=32, 128 threads, 2 CTAs/SM.
// R10 structure (prefetch-before-wait, inline PV) + end-of-iter sync to close
// the stage-overwrite race: load(j+2) writes K/V stage j&1, whose readers
// (S(j), PV(j)) all complete before the end-sync of iter j.
// smem: Qh [0,16K) Ql [16K,32K) | K 2 stages @32K | V 2 stages @64K = 96K.
// ============================================================================
#define A_SK 32768
#define A_SV 65536
#define ATT_SMEM 98304

__global__ void __launch_bounds__(128, 2)
attn_mma(const __nv_bfloat16* __restrict__ qh, const __nv_bfloat16* __restrict__ ql,
         const __nv_bfloat16* __restrict__ kh, const __nv_bfloat16* __restrict__ kl,
         const __nv_bfloat16* __restrict__ vth, const __nv_bfloat16* __restrict__ vtl,
         __nv_bfloat16* __restrict__ ch, __nv_bfloat16* __restrict__ cl)
{
    extern __shared__ char smem[];
    const uint32_t sb = smem_u32(smem);
    const int t    = threadIdx.x;
    const int lane = t & 31;
    const int w    = t >> 5;                                 // 0..3
    const int qt   = (int)gridDim.x - 1 - (int)blockIdx.x;   // heavy tiles first
    const int bh   = blockIdx.y;

    const int lr16  = lane & 15;
    const int lhalf = lane >> 4;
    const int gid   = lane >> 2;
    const int qd    = lane & 3;

    // ---- load Q tile (64 x 128 bf16, hi+lo), once ----
    #pragma unroll
    for (int it = 0; it < 8; it++) {
        int idx = t + it * 128;
        int row = idx >> 4, c = idx & 15;
        uint32_t sw = (uint32_t)(row * 256 + ((c ^ (row & 7)) << 4));
        size_t gq = (((size_t)bh * S_LEN) + qt * 64 + row) * HD + c * 8;
        cp16(sb +         sw, qh + gq);
        cp16(sb + 16384 + sw, ql + gq);
    }

    auto load_kv = [&](int j, int buf) {
        const uint32_t stK = sb + A_SK + buf * 16384;
        const uint32_t stV = sb + A_SV + buf * 16384;
        #pragma unroll
        for (int it = 0; it < 4; it++) {
            int idx = t + it * 128;
            int rowK = idx >> 4, cK = idx & 15;              // 32 rows x 16 chunks
            uint32_t swK = (uint32_t)(rowK * 256 + ((cK ^ (rowK & 7)) << 4));
            size_t gk = (((size_t)bh * S_LEN) + j * 32 + rowK) * HD + cK * 8;
            cp16(stK +        swK, kh + gk);
            cp16(stK + 8192 + swK, kl + gk);
            int rowV = idx >> 2, cV = idx & 3;               // 128 D-rows x 4 chunks
            uint32_t swV = sw64(rowV, cV);
            size_t gv = (((size_t)bh * HD) + rowV) * S_LEN + j * 32 + cV * 8;
            cp16(stV +        swV, vth + gv);
            cp16(stV + 8192 + swV, vtl + gv);
        }
    };

    load_kv(0, 0);
    CP_COMMIT();

    float oacc[16][4];
    #pragma unroll
    for (int i = 0; i < 16; i++)
        #pragma unroll
        for (int c = 0; c < 4; c++) oacc[i][c] = 0.f;
    float mp0 = -1e30f, mp1 = -1e30f, ls0 = 0.f, ls1 = 0.f;

    const float scale = 0.088388347648318447f;  // 1/sqrt(128)
    const int jmax = 2 * qt + 1;
    const int row0g = qt * 64 + w * 16 + gid;
    const int row1g = row0g + 8;

    for (int j = 0; j <= jmax; j++) {
        if (j + 1 <= jmax) load_kv(j + 1, (j + 1) & 1);
        CP_COMMIT();
        CP_WAIT1();
        __syncthreads();

        const uint32_t stKh = sb + A_SK + (j & 1) * 16384;
        const uint32_t stKl = stKh + 8192;
        const uint32_t stVh = sb + A_SV + (j & 1) * 16384;
        const uint32_t stVl = stVh + 8192;

        // ---- S = Q K^T (warp: 16 rows x 32 cols) ----
        float sacc[4][4];
        #pragma unroll
        for (int i = 0; i < 4; i++)
            #pragma unroll
            for (int c = 0; c < 4; c++) sacc[i][c] = 0.f;

        #pragma unroll
        for (int kd = 0; kd < 8; kd++) {
            const int c16 = kd * 2 + lhalf;
            int rowA = w * 16 + lr16;
            uint32_t offA = (uint32_t)(rowA * 256 + ((c16 ^ (rowA & 7)) << 4));
            uint32_t ah4[4], al4[4];
            ldsm4(ah4, sb +         offA);
            ldsm4(al4, sb + 16384 + offA);
            #pragma unroll
            for (int nb = 0; nb < 2; nb++) {
                int rowB = nb * 16 + lr16;
                uint32_t offB = (uint32_t)(rowB * 256 + ((c16 ^ (rowB & 7)) << 4));
                uint32_t bh4[4], bl4[4];
                ldsm4(bh4, stKh + offB);
                ldsm4(bl4, stKl + offB);
                mma16816(sacc[2*nb],   ah4, bh4[0], bh4[2]);
                mma16816(sacc[2*nb],   ah4, bl4[0], bl4[2]);
                mma16816(sacc[2*nb],   al4, bh4[0], bh4[2]);
                mma16816(sacc[2*nb+1], ah4, bh4[1], bh4[3]);
                mma16816(sacc[2*nb+1], ah4, bl4[1], bl4[3]);
                mma16816(sacc[2*nb+1], al4, bh4[1], bh4[3]);
            }
        }

        // ---- online softmax ----
        const bool need_mask = (j * 32 + 31) > (qt * 64 + w * 16);
        float mx0 = -1e30f, mx1 = -1e30f;
        #pragma unroll
        for (int nf = 0; nf < 4; nf++) {
            int colg = j * 32 + nf * 8 + qd * 2;
            float v0 = sacc[nf][0] * scale;
            float v1 = sacc[nf][1] * scale;
            float v2 = sacc[nf][2] * scale;
            float v3 = sacc[nf][3] * scale;
            if (need_mask) {
                if (colg     > row0g) v0 = -1e30f;
                if (colg + 1 > row0g) v1 = -1e30f;
                if (colg     > row1g) v2 = -1e30f;
                if (colg + 1 > row1g) v3 = -1e30f;
            }
            sacc[nf][0] = v0; sacc[nf][1] = v1; sacc[nf][2] = v2; sacc[nf][3] = v3;
            mx0 = fmaxf(mx0, fmaxf(v0, v1));
            mx1 = fmaxf(mx1, fmaxf(v2, v3));
        }
        mx0 = fmaxf(mx0, __shfl_xor_sync(0xffffffffu, mx0, 1));
        mx0 = fmaxf(mx0, __shfl_xor_sync(0xffffffffu, mx0, 2));
        mx1 = fmaxf(mx1, __shfl_xor_sync(0xffffffffu, mx1, 1));
        mx1 = fmaxf(mx1, __shfl_xor_sync(0xffffffffu, mx1, 2));
        float mn0 = fmaxf(mp0, mx0), mn1 = fmaxf(mp1, mx1);
        float a0 = __expf(mp0 - mn0), a1 = __expf(mp1 - mn1);
        mp0 = mn0; mp1 = mn1;
        float pl0 = 0.f, pl1 = 0.f;
        #pragma unroll
        for (int nf = 0; nf < 4; nf++) {
            float p0 = __expf(sacc[nf][0] - mn0);
            float p1 = __expf(sacc[nf][1] - mn0);
            float p2 = __expf(sacc[nf][2] - mn1);
            float p3 = __expf(sacc[nf][3] - mn1);
            sacc[nf][0] = p0; sacc[nf][1] = p1; sacc[nf][2] = p2; sacc[nf][3] = p3;
            pl0 += p0 + p1; pl1 += p2 + p3;
        }
        ls0 = ls0 * a0 + pl0;
        ls1 = ls1 * a1 + pl1;
        #pragma unroll
        for (int nf = 0; nf < 16; nf++) {
            oacc[nf][0] *= a0; oacc[nf][1] *= a0;
            oacc[nf][2] *= a1; oacc[nf][3] *= a1;
        }

        // ---- pack P (hi + residual) ----
        uint32_t ppa[2][4], ppb[2][4];
        #pragma unroll
        for (int ks = 0; ks < 2; ks++) {
            float p00 = sacc[2*ks][0],   p01 = sacc[2*ks][1];
            float p02 = sacc[2*ks][2],   p03 = sacc[2*ks][3];
            float p10 = sacc[2*ks+1][0], p11 = sacc[2*ks+1][1];
            float p12 = sacc[2*ks+1][2], p13 = sacc[2*ks+1][3];
            ppa[ks][0] = pack_bf16x2(p00, p01);
            ppa[ks][1] = pack_bf16x2(p02, p03);
            ppa[ks][2] = pack_bf16x2(p10, p11);
            ppa[ks][3] = pack_bf16x2(p12, p13);
            __nv_bfloat162 h;
            h = *(__nv_bfloat162*)&ppa[ks][0];
            ppb[ks][0] = pack_bf16x2(p00 - __bfloat162float(h.x), p01 - __bfloat162float(h.y));
            h = *(__nv_bfloat162*)&ppa[ks][1];
            ppb[ks][1] = pack_bf16x2(p02 - __bfloat162float(h.x), p03 - __bfloat162float(h.y));
            h = *(__nv_bfloat162*)&ppa[ks][2];
            ppb[ks][2] = pack_bf16x2(p10 - __bfloat162float(h.x), p11 - __bfloat162float(h.y));
            h = *(__nv_bfloat162*)&ppa[ks][3];
            ppb[ks][3] = pack_bf16x2(p12 - __bfloat162float(h.x), p13 - __bfloat162float(h.y));
        }

        // ---- O += P V (V^T as NT B operand) ----
        #pragma unroll
        for (int ks = 0; ks < 2; ks++) {
            const int c = ks * 2 + lhalf;
            #pragma unroll
            for (int nb = 0; nb < 8; nb++) {
                int rowB = nb * 16 + lr16;
                uint32_t offB = sw64(rowB, c);
                uint32_t vh4[4], vl4[4];
                ldsm4(vh4, stVh + offB);
                ldsm4(vl4, stVl + offB);
                mma16816(oacc[2*nb],   ppa[ks], vh4[0], vh4[2]);
                mma16816(oacc[2*nb],   ppa[ks], vl4[0], vl4[2]);
                mma16816(oacc[2*nb],   ppb[ks], vh4[0], vh4[2]);
                mma16816(oacc[2*nb+1], ppa[ks], vh4[1], vh4[3]);
                mma16816(oacc[2*nb+1], ppa[ks], vl4[1], vl4[3]);
                mma16816(oacc[2*nb+1], ppb[ks], vh4[1], vh4[3]);
            }
        }
        __syncthreads();   // race fix: all reads of stage j&1 done before
                           // iter j+1 issues load(j+2) into stage j&1
    }

    // ---- finalize + fused bf16 hi/lo ctx write (B,S,E) ----
    ls0 += __shfl_xor_sync(0xffffffffu, ls0, 1);
    ls0 += __shfl_xor_sync(0xffffffffu, ls0, 2);
    ls1 += __shfl_xor_sync(0xffffffffu, ls1, 1);
    ls1 += __shfl_xor_sync(0xffffffffu, ls1, 2);
    float rn0 = 1.f / ls0, rn1 = 1.f / ls1;

    int b = bh >> 4, h = bh & 15;
    size_t e0 = ((size_t)b * S_LEN + row0g) * EMB + h * HD;
    size_t e1 = e0 + (size_t)8 * EMB;
    #pragma unroll
    for (int nf = 0; nf < 16; nf++) {
        int col = nf * 8 + qd * 2;
        split_store(ch, cl, e0 + col, oacc[nf][0] * rn0, oacc[nf][1] * rn0);
        split_store(ch, cl, e1 + col, oacc[nf][2] * rn1, oacc[nf][3] * rn1);
    }
}

// ============================================================================
// launch
// ============================================================================
extern "C" void kernel_launch(void* const* d_in, const int* in_sizes, int n_in,
                              void* d_out, int out_size)
{
    (void)in_sizes; (void)n_in; (void)out_size;
    const float* x  = (const float*)d_in[0];
    const float* Wq = (const float*)d_in[1];
    const float* Wk = (const float*)d_in[2];
    const float* Wv = (const float*)d_in[3];
    const float* Wo = (const float*)d_in[4];

    float* out  = (float*)d_out;
    float* outK = out  + (size_t)NB * S_LEN * EMB;
    float* outV = outK + (size_t)BHN * S_LEN * HD;

    __nv_bfloat16 *ah, *al, *wh, *wl, *qhp, *qlp, *khp, *klp, *vthp, *vtlp;
    cudaGetSymbolAddress((void**)&ah,   g_ah);
    cudaGetSymbolAddress((void**)&al,   g_al);
    cudaGetSymbolAddress((void**)&wh,   g_wh);
    cudaGetSymbolAddress((void**)&wl,   g_wl);
    cudaGetSymbolAddress((void**)&qhp,  g_qh);
    cudaGetSymbolAddress((void**)&qlp,  g_ql);
    cudaGetSymbolAddress((void**)&khp,  g_kh);
    cudaGetSymbolAddress((void**)&klp,  g_kl);
    cudaGetSymbolAddress((void**)&vthp, g_vth);
    cudaGetSymbolAddress((void**)&vtlp, g_vtl);

    cudaFuncSetAttribute(attn_mma,
                         cudaFuncAttributeMaxDynamicSharedMemorySize, ATT_SMEM);
    cudaFuncSetAttribute(gemm_qkv,
                         cudaFuncAttributeMaxDynamicSharedMemorySize, GEMM_SMEM);
    cudaFuncSetAttribute(gemm_wo,
                         cudaFuncAttributeMaxDynamicSharedMemorySize, GEMM_SMEM);

    const size_t woff = (size_t)EMB * EMB;

    int n4x = M_TOT * EMB / 4;
    int n4w = EMB * EMB / 4;
    int n4tot = n4x + 4 * n4w;
    split_all<<<(n4tot + 255) / 256, 256>>>((const float4*)x,
        (const float4*)Wq, (const float4*)Wk, (const float4*)Wv, (const float4*)Wo,
        ah, al, wh, wl, n4x, n4w);

    // fused QKV projection (+RoPE/split for Q,K), one launch, 128-thr CTAs
    gemm_qkv<<<dim3(EMB / 64, M_TOT / 128, 3), 128, GEMM_SMEM>>>(
        ah, al, wh, wl, qhp, qlp, khp, klp, outK, outV);

    vsplit_t<<<dim3(S_LEN / 32, HD / 32, BHN), dim3(32, 8)>>>(outV, vthp, vtlp);

    // attention writes ctx directly as bf16 hi/lo into ah/al
    attn_mma<<<dim3(S_LEN / 64, BHN), 128, ATT_SMEM>>>(qhp, qlp, khp, klp,
                                                       vthp, vtlp, ah, al);

    gemm_wo<<<dim3(EMB / 64, M_TOT / 128), 128, GEMM_SMEM>>>(
        ah, al, wh + 3*woff, wl + 3*woff, out);
}